// round 11
// baseline (speedup 1.0000x reference)
#include <cuda_runtime.h>

// QuantizationLayer: out[b, 3n+i] = bit (2-i) of round_half_even(x[b,n]*8 - 0.5)
// x: [65536, 512] fp32 -> q in [0,7] -> 3 bits MSB-first as fp32 0/1.
//
// R3 kernel, eighth resubmit (R3/R5-R10: GPU acquisition timeouts, R4:
// container failed twice — all infra; this kernel has not run since R2).
// Persistent grid-stride kernel (148 SM x 8 CTA x 256 thr) to kill the
// ~28-wave launch/retire churn, plus streaming cache hints (__ldcs/__stcs):
// neither stream is ever re-read, so L2 should evict early.
// Per tile: 1 LDG.128 -> quantize 4 elems -> 12 floats staged in smem ->
// 3 coalesced STG.128 per lane (96 contiguous float4 per warp).

__global__ void __launch_bounds__(256) quant_bits_kernel(
    const float4* __restrict__ in, float4* __restrict__ out, int n4)
{
    __shared__ float4 stage[8][96];   // 8 warps * 96 float4 = 12 KB

    const int warp = threadIdx.x >> 5;
    const int lane = threadIdx.x & 31;
    const int stride = gridDim.x * blockDim.x;   // multiple of 32

    for (int t = blockIdx.x * blockDim.x + threadIdx.x; t < n4; t += stride) {
        float4 v = __ldcs(in + t);

        // round-half-even(x*8 - 0.5): both fp ops exact, F2I.RN ties-to-even.
        int q0 = __float2int_rn(v.x * 8.0f - 0.5f);
        int q1 = __float2int_rn(v.y * 8.0f - 0.5f);
        int q2 = __float2int_rn(v.z * 8.0f - 0.5f);
        int q3 = __float2int_rn(v.w * 8.0f - 0.5f);

        float4 o0, o1, o2;
        o0.x = (float)((q0 >> 2) & 1);
        o0.y = (float)((q0 >> 1) & 1);
        o0.z = (float)( q0       & 1);
        o0.w = (float)((q1 >> 2) & 1);
        o1.x = (float)((q1 >> 1) & 1);
        o1.y = (float)( q1       & 1);
        o1.z = (float)((q2 >> 2) & 1);
        o1.w = (float)((q2 >> 1) & 1);
        o2.x = (float)( q2       & 1);
        o2.y = (float)((q3 >> 2) & 1);
        o2.z = (float)((q3 >> 1) & 1);
        o2.w = (float)( q3       & 1);

        // Stage: byte stride 48/lane -> conflict-free STS.128.
        stage[warp][3 * lane + 0] = o0;
        stage[warp][3 * lane + 1] = o1;
        stage[warp][3 * lane + 2] = o2;
        __syncwarp();

        // Coalesced streaming writeback: warp's 96 contiguous float4s.
        int base = (t >> 5) * 96;
        __stcs(&out[base + lane     ], stage[warp][lane     ]);
        __stcs(&out[base + lane + 32], stage[warp][lane + 32]);
        __stcs(&out[base + lane + 64], stage[warp][lane + 64]);
        __syncwarp();   // protect stage before next iteration's STS
    }
}

extern "C" void kernel_launch(void* const* d_in, const int* in_sizes, int n_in,
                              void* d_out, int out_size)
{
    const float4* in = (const float4*)d_in[0];
    float4* out = (float4*)d_out;
    int n = in_sizes[0];          // 33,554,432 elements
    int n4 = n / 4;               // 8,388,608 float4 tiles

    int threads = 256;
    int blocks = 148 * 8;         // persistent: 8 CTAs per SM
    quant_bits_kernel<<<blocks, threads>>>(in, out, n4);
}

// round 15
// speedup vs baseline: 1.2034x; 1.2034x over previous
#include <cuda_runtime.h>

// QuantizationLayer: out[b, 3n+i] = bit (2-i) of round_half_even(x[b,n]*8 - 0.5)
// x: [65536, 512] fp32 -> q in [0,7] -> 3 bits MSB-first as fp32 0/1.
//
// R12 kernel, third resubmit (R12/R13/R14 benches were GPU-acquisition
// timeouts; this version has never run).
// R2's one-shot oversubscribed grid (32768 CTAs -- CTA oversubscription is
// the MLP engine; R11 proved the persistent loop's barrier-serialized
// iterations cost 16%). Single isolated change vs R2: streaming cache hints
// (__ldcs/__stcs) on the touch-once streams.
// Per thread: 1 LDG.128 -> quantize 4 elems -> 12 floats staged in smem ->
// 3 coalesced STG.128 per lane (96 contiguous float4 per warp).

__global__ void __launch_bounds__(256) quant_bits_kernel(
    const float4* __restrict__ in, float4* __restrict__ out, int n4)
{
    __shared__ float4 stage[8][96];   // 8 warps * 96 float4 = 12 KB

    int t = blockIdx.x * blockDim.x + threadIdx.x;
    if (t >= n4) return;              // n4 % 256 == 0: whole warps exit together

    int warp = threadIdx.x >> 5;
    int lane = threadIdx.x & 31;

    float4 v = __ldcs(in + t);

    // round-half-even(x*8 - 0.5): both fp ops exact, F2I.RN ties-to-even.
    int q0 = __float2int_rn(v.x * 8.0f - 0.5f);
    int q1 = __float2int_rn(v.y * 8.0f - 0.5f);
    int q2 = __float2int_rn(v.z * 8.0f - 0.5f);
    int q3 = __float2int_rn(v.w * 8.0f - 0.5f);

    float4 o0, o1, o2;
    o0.x = (float)((q0 >> 2) & 1);
    o0.y = (float)((q0 >> 1) & 1);
    o0.z = (float)( q0       & 1);
    o0.w = (float)((q1 >> 2) & 1);
    o1.x = (float)((q1 >> 1) & 1);
    o1.y = (float)( q1       & 1);
    o1.z = (float)((q2 >> 2) & 1);
    o1.w = (float)((q2 >> 1) & 1);
    o2.x = (float)( q2       & 1);
    o2.y = (float)((q3 >> 2) & 1);
    o2.z = (float)((q3 >> 1) & 1);
    o2.w = (float)( q3       & 1);

    // Stage: byte stride 48/lane -> conflict-free STS.128.
    stage[warp][3 * lane + 0] = o0;
    stage[warp][3 * lane + 1] = o1;
    stage[warp][3 * lane + 2] = o2;
    __syncwarp();

    // Coalesced streaming writeback: warp's 96 contiguous float4s.
    int base = (t >> 5) * 96;
    __stcs(&out[base + lane     ], stage[warp][lane     ]);
    __stcs(&out[base + lane + 32], stage[warp][lane + 32]);
    __stcs(&out[base + lane + 64], stage[warp][lane + 64]);
}

extern "C" void kernel_launch(void* const* d_in, const int* in_sizes, int n_in,
                              void* d_out, int out_size)
{
    const float4* in = (const float4*)d_in[0];
    float4* out = (float4*)d_out;
    int n = in_sizes[0];          // 33,554,432 elements
    int n4 = n / 4;               // 8,388,608 float4 tiles

    int threads = 256;
    int blocks = (n4 + threads - 1) / threads;   // 32768 one-shot CTAs
    quant_bits_kernel<<<blocks, threads>>>(in, out, n4);
}